// round 15
// baseline (speedup 1.0000x reference)
#include <cuda_runtime.h>
#include <cuda_fp16.h>
#include <cstdint>
#include <type_traits>

// Problem constants (fixed by setup_inputs)
#define N0 20000      // nodes
#define EE 640000     // edges
#define HH 128        // hidden
#define DD 3          // edge-attr dims
#define RR 8          // relations

#define TXSZ ((size_t)RR * N0 * HH)
#define DYN_SMEM (128 * 132 * 4)   // 67584 B: fp32 C-staging (aliases sA/sB)

// Scratch (static device globals; no allocation allowed)
__device__ __half   g_h0[(size_t)N0 * HH];        // 5.1 MB  (fp16)
__device__ __half   g_h1[(size_t)3 * N0 * HH];    // 15.4 MB (fp16)
__device__ __half   g_txh[3][TXSZ];               // 3 x 41 MB (per-j, enables overlap)
__device__ float    g_inv[DD * RR * N0];          // 1.9 MB
__device__ int      g_deg[N0];
__device__ int      g_off[N0];
__device__ int      g_pos[N0];
__device__ int      g_total;
__device__ uint32_t g_plj[3][EE];                 // 7.7 MB : per-j packed (r<<29)|src
__device__ __half2  g_wh[24 * 16 * 256];          // 393 KB : fp16 W, sW-interleaved

// ---------------------------------------------------------------------------
__device__ __forceinline__ void mma_f16(float* c, const uint32_t* a, const uint32_t* b) {
    asm volatile("mma.sync.aligned.m16n8k16.row.col.f32.f16.f16.f32 "
                 "{%0,%1,%2,%3},{%4,%5,%6,%7},{%8,%9},{%0,%1,%2,%3};"
                 : "+f"(c[0]), "+f"(c[1]), "+f"(c[2]), "+f"(c[3])
                 : "r"(a[0]), "r"(a[1]), "r"(a[2]), "r"(a[3]), "r"(b[0]), "r"(b[1]));
}

// ---------------------------------------------------------------------------
// Weight precompute: cw fp32 -> g_wh fp16, interleaved for direct sW copies.
// ---------------------------------------------------------------------------
__global__ void wcvt_kernel(const float* __restrict__ cw) {
    int idx = blockIdx.x * blockDim.x + threadIdx.x;
    if (idx >= 24 * 16 * 256) return;
    int col = idx & 255;           // r*32 + d
    int c2  = (idx >> 8) & 15;     // c-pair
    int ljb = idx >> 12;           // (l*3+j)*4 + b
    int b = ljb & 3, lj = ljb >> 2;
    int r = col >> 5, d = col & 31;
    size_t base = ((((size_t)(lj * 8 + r) * 4 + b) * 32 + 2 * c2) * 32) + d;
    g_wh[idx] = __floats2half2_rn(cw[base], cw[base + 32]);
}

// ---------------------------------------------------------------------------
// CSR build + inverse counts
// ---------------------------------------------------------------------------
__global__ void zero_kernel() {
    int i = blockIdx.x * blockDim.x + threadIdx.x;
    if (i < DD * RR * N0) g_inv[i] = 0.f;
    if (i == 0) g_total = 0;
}

__global__ void count_kernel(const int* __restrict__ ei, const int* __restrict__ ea) {
    int e = blockIdx.x * blockDim.x + threadIdx.x;
    if (e >= EE) return;
    int dd = ei[EE + e];
#pragma unroll
    for (int j = 0; j < DD; j++) {
        int r = ea[e * DD + j];
        atomicAdd(&g_inv[(j * RR + r) * N0 + dd], 1.0f);
    }
}

// runs BEFORE inv_kernel: derives deg from the j=0 relation counts
__global__ void offsets_kernel() {
    int d = blockIdx.x * blockDim.x + threadIdx.x;
    if (d >= N0) return;
    float s = 0.f;
#pragma unroll
    for (int r = 0; r < RR; r++) s += g_inv[r * N0 + d];
    int dg = (int)s;
    int o = atomicAdd(&g_total, dg);
    g_deg[d] = dg;
    g_off[d] = o;
    g_pos[d] = o;
}

__global__ void inv_kernel() {
    int i = blockIdx.x * blockDim.x + threadIdx.x;
    if (i < DD * RR * N0) {
        float c = g_inv[i];
        g_inv[i] = 1.0f / fmaxf(c, 1.0f);
    }
}

__global__ void fill_kernel(const int* __restrict__ ei, const int* __restrict__ ea) {
    int e = blockIdx.x * blockDim.x + threadIdx.x;
    if (e >= EE) return;
    uint32_t s = (uint32_t)ei[e];
    int dd = ei[EE + e];
    uint32_t r0 = (uint32_t)ea[e * DD + 0];
    uint32_t r1 = (uint32_t)ea[e * DD + 1];
    uint32_t r2 = (uint32_t)ea[e * DD + 2];
    int p = atomicAdd(&g_pos[dd], 1);
    g_plj[0][p] = (r0 << 29) | s;
    g_plj[1][p] = (r1 << 29) | s;
    g_plj[2][p] = (r2 << 29) | s;
}

// ---------------------------------------------------------------------------
// Plain fp16 GEMM (femb only): out[M,128] = A[M,K] @ B[K,128]. A fp32, out fp16.
// ---------------------------------------------------------------------------
__global__ void __launch_bounds__(256, 2)
gemm_f16(const float* __restrict__ A, const float* __restrict__ B,
         __half* __restrict__ out, int M, int K) {
    __shared__ __half  sA[128][40];
    __shared__ __half2 sB[16][136];
    int m0   = blockIdx.x * 128;
    int wid  = threadIdx.x >> 5, lane = threadIdx.x & 31;
    int mw   = wid >> 1, nw = wid & 1;
    int gid  = lane >> 2, qid = lane & 3;

    float c[2][8][4];
#pragma unroll
    for (int mt = 0; mt < 2; mt++)
#pragma unroll
        for (int nt = 0; nt < 8; nt++)
#pragma unroll
            for (int q = 0; q < 4; q++) c[mt][nt][q] = 0.f;

    for (int k0 = 0; k0 < K; k0 += 32) {
#pragma unroll
        for (int it = 0; it < 4; it++) {
            int idx = threadIdx.x + it * 256;
            int m = idx >> 3, k4 = (idx & 7) * 4;
            float4 v = make_float4(0.f, 0.f, 0.f, 0.f);
            if (m0 + m < M) v = *(const float4*)&A[(size_t)(m0 + m) * K + k0 + k4];
            *(__half2*)&sA[m][k4]     = __floats2half2_rn(v.x, v.y);
            *(__half2*)&sA[m][k4 + 2] = __floats2half2_rn(v.z, v.w);
        }
#pragma unroll
        for (int it = 0; it < 2; it++) {
            int idx = threadIdx.x + it * 256;
            int r2 = idx >> 5, c4 = (idx & 31) * 4;
            float4 u = *(const float4*)&B[(size_t)(k0 + 2 * r2) * HH + c4];
            float4 w = *(const float4*)&B[(size_t)(k0 + 2 * r2 + 1) * HH + c4];
            sB[r2][c4 + 0] = __floats2half2_rn(u.x, w.x);
            sB[r2][c4 + 1] = __floats2half2_rn(u.y, w.y);
            sB[r2][c4 + 2] = __floats2half2_rn(u.z, w.z);
            sB[r2][c4 + 3] = __floats2half2_rn(u.w, w.w);
        }
        __syncthreads();
#pragma unroll
        for (int ks = 0; ks < 32; ks += 16) {
            uint32_t a[2][4], b[8][2];
#pragma unroll
            for (int mt = 0; mt < 2; mt++) {
                int r = mw * 32 + mt * 16 + gid;
                a[mt][0] = *(const uint32_t*)&sA[r][ks + qid * 2];
                a[mt][1] = *(const uint32_t*)&sA[r + 8][ks + qid * 2];
                a[mt][2] = *(const uint32_t*)&sA[r][ks + qid * 2 + 8];
                a[mt][3] = *(const uint32_t*)&sA[r + 8][ks + qid * 2 + 8];
            }
            int kp = ks >> 1;
#pragma unroll
            for (int nt = 0; nt < 8; nt++) {
                int cn = nw * 64 + nt * 8 + gid;
                b[nt][0] = *(const uint32_t*)&sB[kp + qid][cn];
                b[nt][1] = *(const uint32_t*)&sB[kp + qid + 4][cn];
            }
#pragma unroll
            for (int mt = 0; mt < 2; mt++)
#pragma unroll
                for (int nt = 0; nt < 8; nt++) mma_f16(c[mt][nt], a[mt], b[nt]);
        }
        __syncthreads();
    }

#pragma unroll
    for (int mt = 0; mt < 2; mt++) {
        int row0 = m0 + mw * 32 + mt * 16 + gid;
        int row1 = row0 + 8;
#pragma unroll
        for (int nt = 0; nt < 8; nt++) {
            int col = nw * 64 + nt * 8 + qid * 2;
            if (row0 < M)
                *(__half2*)&out[(size_t)row0 * HH + col] = __floats2half2_rn(c[mt][nt][0], c[mt][nt][1]);
            if (row1 < M)
                *(__half2*)&out[(size_t)row1 * HH + col] = __floats2half2_rn(c[mt][nt][2], c[mt][nt][3]);
        }
    }
}

// ---------------------------------------------------------------------------
// Fused root-GEMM + aggregation + bias + ReLU (per conv).
// out[dst] = relu( (h @ root)[dst] + bias + sum_e inv[r_e,dst]*txh[r_e][src_e] )
// (agg term only for dst < N0; rows >= N0 get relu(gemm+bias) — layer-1 tail.)
// Mainloop = gemm_f16 (A fp16, K=128). C staged in fp32 DYNAMIC smem aliasing
// sA/sB; then warp w handles rows w, w+8, ..., w+120: CSR edge-gather, add
// staged+bias, relu, single coalesced store. Saves the out write+read round
// trip of the old gemm->agg pair.
// ---------------------------------------------------------------------------
template <typename TO>
__global__ void __launch_bounds__(256, 2)
gemm_agg(const __half* __restrict__ A, const float* __restrict__ B,
         const float* __restrict__ bias, const __half* __restrict__ txh,
         const uint32_t* __restrict__ pl, const float* __restrict__ inv,
         TO* __restrict__ out, int M) {
    extern __shared__ __align__(16) char dyn[];
    __half  (*sA)[40]  = (__half(*)[40])dyn;                 // 10240 B
    __half2 (*sB)[136] = (__half2(*)[136])(dyn + 10240);     // 8704 B
    float   (*sC)[132] = (float(*)[132])dyn;                 // 67584 B (post-MMA alias)

    int m0   = blockIdx.x * 128;
    int wid  = threadIdx.x >> 5, lane = threadIdx.x & 31;
    int mw   = wid >> 1, nw = wid & 1;
    int gid  = lane >> 2, qid = lane & 3;

    float c[2][8][4];
#pragma unroll
    for (int mt = 0; mt < 2; mt++)
#pragma unroll
        for (int nt = 0; nt < 8; nt++)
#pragma unroll
            for (int q = 0; q < 4; q++) c[mt][nt][q] = 0.f;

#pragma unroll
    for (int k0 = 0; k0 < HH; k0 += 32) {
        // A tile 128x32 fp16 (256 uint4 x 2)
#pragma unroll
        for (int it = 0; it < 2; it++) {
            int idx = threadIdx.x + it * 256;
            int m = idx >> 2, k8 = (idx & 3) * 8;
            uint4 v = make_uint4(0, 0, 0, 0);
            if (m0 + m < M) v = *(const uint4*)&A[(size_t)(m0 + m) * HH + k0 + k8];
            *(uint2*)&sA[m][k8]     = make_uint2(v.x, v.y);
            *(uint2*)&sA[m][k8 + 4] = make_uint2(v.z, v.w);
        }
        // B tile 32x128 fp32 -> k-pair interleaved half2
#pragma unroll
        for (int it = 0; it < 2; it++) {
            int idx = threadIdx.x + it * 256;
            int r2 = idx >> 5, c4 = (idx & 31) * 4;
            float4 u = *(const float4*)&B[(size_t)(k0 + 2 * r2) * HH + c4];
            float4 w = *(const float4*)&B[(size_t)(k0 + 2 * r2 + 1) * HH + c4];
            sB[r2][c4 + 0] = __floats2half2_rn(u.x, w.x);
            sB[r2][c4 + 1] = __floats2half2_rn(u.y, w.y);
            sB[r2][c4 + 2] = __floats2half2_rn(u.z, w.z);
            sB[r2][c4 + 3] = __floats2half2_rn(u.w, w.w);
        }
        __syncthreads();
#pragma unroll
        for (int ks = 0; ks < 32; ks += 16) {
            uint32_t a[2][4], b[8][2];
#pragma unroll
            for (int mt = 0; mt < 2; mt++) {
                int r = mw * 32 + mt * 16 + gid;
                a[mt][0] = *(const uint32_t*)&sA[r][ks + qid * 2];
                a[mt][1] = *(const uint32_t*)&sA[r + 8][ks + qid * 2];
                a[mt][2] = *(const uint32_t*)&sA[r][ks + qid * 2 + 8];
                a[mt][3] = *(const uint32_t*)&sA[r + 8][ks + qid * 2 + 8];
            }
            int kp = ks >> 1;
#pragma unroll
            for (int nt = 0; nt < 8; nt++) {
                int cn = nw * 64 + nt * 8 + gid;
                b[nt][0] = *(const uint32_t*)&sB[kp + qid][cn];
                b[nt][1] = *(const uint32_t*)&sB[kp + qid + 4][cn];
            }
#pragma unroll
            for (int mt = 0; mt < 2; mt++)
#pragma unroll
                for (int nt = 0; nt < 8; nt++) mma_f16(c[mt][nt], a[mt], b[nt]);
        }
        __syncthreads();   // final iter: all sA/sB reads done -> safe to alias sC
    }

    // stage C (raw, no bias) into fp32 smem
#pragma unroll
    for (int mt = 0; mt < 2; mt++) {
        int rl0 = mw * 32 + mt * 16 + gid;
#pragma unroll
        for (int nt = 0; nt < 8; nt++) {
            int col = nw * 64 + nt * 8 + qid * 2;
            *(float2*)&sC[rl0][col]     = make_float2(c[mt][nt][0], c[mt][nt][1]);
            *(float2*)&sC[rl0 + 8][col] = make_float2(c[mt][nt][2], c[mt][nt][3]);
        }
    }
    __syncthreads();

    // agg + bias + relu + store. Warp w: rows w, w+8, ..., w+120.
    float4 bv = *(const float4*)&bias[lane * 4];
    for (int it = 0; it < 16; it++) {
        int rl = wid + it * 8;
        int dst = m0 + rl;
        if (dst >= M) break;
        float4 acc = make_float4(0.f, 0.f, 0.f, 0.f);
        if (dst < N0) {
            int o = g_off[dst];
            int n = g_deg[dst];
            int i = 0;
            for (; i + 8 <= n; i += 8) {
                uint32_t p[8];
#pragma unroll
                for (int u = 0; u < 8; u++) p[u] = __ldg(&pl[o + i + u]);
#pragma unroll
                for (int u = 0; u < 8; u++) {
                    int r = p[u] >> 29, s = p[u] & 0x1FFFFFFF;
                    float w = __ldg(&inv[r * N0 + dst]);
                    uint2 g = __ldg((const uint2*)&txh[((size_t)r * N0 + s) * HH + lane * 4]);
                    float2 f01 = __half22float2(*(__half2*)&g.x);
                    float2 f23 = __half22float2(*(__half2*)&g.y);
                    acc.x += w * f01.x; acc.y += w * f01.y;
                    acc.z += w * f23.x; acc.w += w * f23.y;
                }
            }
            for (; i < n; i++) {
                uint32_t p0 = __ldg(&pl[o + i]);
                int r = p0 >> 29, s = p0 & 0x1FFFFFFF;
                float w = __ldg(&inv[r * N0 + dst]);
                uint2 g = __ldg((const uint2*)&txh[((size_t)r * N0 + s) * HH + lane * 4]);
                float2 f01 = __half22float2(*(__half2*)&g.x);
                float2 f23 = __half22float2(*(__half2*)&g.y);
                acc.x += w * f01.x; acc.y += w * f01.y;
                acc.z += w * f23.x; acc.w += w * f23.y;
            }
        }
        float4 base = *(float4*)&sC[rl][lane * 4];
        float v0 = fmaxf(base.x + bv.x + acc.x, 0.f);
        float v1 = fmaxf(base.y + bv.y + acc.y, 0.f);
        float v2 = fmaxf(base.z + bv.z + acc.z, 0.f);
        float v3 = fmaxf(base.w + bv.w + acc.w, 0.f);
        if constexpr (std::is_same<TO, float>::value) {
            *(float4*)&out[(size_t)dst * HH + lane * 4] = make_float4(v0, v1, v2, v3);
        } else {
            __half2 o01 = __floats2half2_rn(v0, v1);
            __half2 o23 = __floats2half2_rn(v2, v3);
            *(uint2*)&out[(size_t)dst * HH + lane * 4] =
                make_uint2(*(uint32_t*)&o01, *(uint32_t*)&o23);
        }
    }
}

// ---------------------------------------------------------------------------
// fp16 tx: grid (ceil(N0/128), 4). Block loads its b-slice of W ONCE (16KB fp16
// copy from g_wh), then two 64-node subtiles; staged coalesced epilogue.
// ---------------------------------------------------------------------------
__global__ void __launch_bounds__(256, 2)
tx_f16(const __half* __restrict__ h, const __half2* __restrict__ wh, __half* __restrict__ dst) {
    __shared__ __half  sA[64][40];
    __shared__ __half2 sW[16][264];
    __shared__ __half  sC[32][264];
    int base0 = blockIdx.x * 128;
    int b     = blockIdx.y;
    int wid = threadIdx.x >> 5, lane = threadIdx.x & 31;
    int mw  = wid & 1;
    int nw  = wid >> 1;
    int gid = lane >> 2, qid = lane & 3;

    const __half2* whb = wh + (size_t)b * 4096;
#pragma unroll
    for (int it = 0; it < 4; it++) {
        int idx = threadIdx.x + it * 256;
        int c2 = idx >> 6, u = idx & 63;
        *(uint4*)&sW[c2][u * 4] = *(const uint4*)&whb[c2 * 256 + u * 4];
    }

#pragma unroll
    for (int t = 0; t < 2; t++) {
        int n0 = base0 + t * 64;
        {
            int node = threadIdx.x >> 2, k8 = (threadIdx.x & 3) * 8;
            uint4 v = make_uint4(0, 0, 0, 0);
            if (n0 + node < N0) v = *(const uint4*)&h[(size_t)(n0 + node) * HH + b * 32 + k8];
            *(uint2*)&sA[node][k8]     = make_uint2(v.x, v.y);
            *(uint2*)&sA[node][k8 + 4] = make_uint2(v.z, v.w);
        }
        __syncthreads();

        float c[2][8][4];
#pragma unroll
        for (int mt = 0; mt < 2; mt++)
#pragma unroll
            for (int nt = 0; nt < 8; nt++)
#pragma unroll
                for (int q = 0; q < 4; q++) c[mt][nt][q] = 0.f;

#pragma unroll
        for (int ks = 0; ks < 32; ks += 16) {
            uint32_t a[2][4], bb[8][2];
#pragma unroll
            for (int mt = 0; mt < 2; mt++) {
                int r = mw * 32 + mt * 16 + gid;
                a[mt][0] = *(const uint32_t*)&sA[r][ks + qid * 2];
                a[mt][1] = *(const uint32_t*)&sA[r + 8][ks + qid * 2];
                a[mt][2] = *(const uint32_t*)&sA[r][ks + qid * 2 + 8];
                a[mt][3] = *(const uint32_t*)&sA[r + 8][ks + qid * 2 + 8];
            }
            int kp = ks >> 1;
#pragma unroll
            for (int nt = 0; nt < 8; nt++) {
                int cn = nw * 64 + nt * 8 + gid;
                bb[nt][0] = *(const uint32_t*)&sW[kp + qid][cn];
                bb[nt][1] = *(const uint32_t*)&sW[kp + qid + 4][cn];
            }
#pragma unroll
            for (int mt = 0; mt < 2; mt++)
#pragma unroll
                for (int nt = 0; nt < 8; nt++) mma_f16(c[mt][nt], a[mt], bb[nt]);
        }

#pragma unroll
        for (int hf = 0; hf < 2; hf++) {
            __syncthreads();
            if (mw == hf) {
#pragma unroll
                for (int mt = 0; mt < 2; mt++) {
                    int rl = mt * 16 + gid;
#pragma unroll
                    for (int nt = 0; nt < 8; nt++) {
                        int col = nw * 64 + nt * 8 + qid * 2;
                        *(__half2*)&sC[rl][col]     = __floats2half2_rn(c[mt][nt][0], c[mt][nt][1]);
                        *(__half2*)&sC[rl + 8][col] = __floats2half2_rn(c[mt][nt][2], c[mt][nt][3]);
                    }
                }
            }
            __syncthreads();
            int rr = lane >> 2;
            int d8 = lane & 3;
#pragma unroll
            for (int it2 = 0; it2 < 4; it2++) {
                int rl = wid + it2 * 8;
                int node = n0 + hf * 32 + rl;
                if (node < N0) {
                    uint4 v = *(const uint4*)&sC[rl][rr * 32 + d8 * 8];
                    *(uint4*)&dst[((size_t)rr * N0 + node) * HH + b * 32 + d8 * 8] = v;
                }
            }
        }
        __syncthreads();
    }
}

// ---------------------------------------------------------------------------
// Streams/events (4 streams — the 7-stream R14 graph tripped the harness's
// graph-upload memory check; R13's 4-stream topology is known clean).
// cudaFuncSetAttribute for the dynamic-smem fused kernels happens here (pre-
// capture, no allocation).
// ---------------------------------------------------------------------------
namespace {
struct Ctx {
    cudaStream_t sc, sj[3];
    cudaEvent_t  eFork, eCsr, eH0, eA0[3], eDone[3];
    Ctx() {
        cudaStreamCreateWithFlags(&sc, cudaStreamNonBlocking);
        for (int i = 0; i < 3; i++) cudaStreamCreateWithFlags(&sj[i], cudaStreamNonBlocking);
        cudaEventCreateWithFlags(&eFork, cudaEventDisableTiming);
        cudaEventCreateWithFlags(&eCsr,  cudaEventDisableTiming);
        cudaEventCreateWithFlags(&eH0,   cudaEventDisableTiming);
        for (int i = 0; i < 3; i++) {
            cudaEventCreateWithFlags(&eA0[i],   cudaEventDisableTiming);
            cudaEventCreateWithFlags(&eDone[i], cudaEventDisableTiming);
        }
        cudaFuncSetAttribute(gemm_agg<float>,
                             cudaFuncAttributeMaxDynamicSharedMemorySize, DYN_SMEM);
        cudaFuncSetAttribute(gemm_agg<__half>,
                             cudaFuncAttributeMaxDynamicSharedMemorySize, DYN_SMEM);
    }
};
Ctx g_ctx;  // constructed at load time
}

// ---------------------------------------------------------------------------
extern "C" void kernel_launch(void* const* d_in, const int* in_sizes, int n_in,
                              void* d_out, int out_size) {
    const float* x    = (const float*)d_in[0];   // (N0, 64)
    const int*   ei   = (const int*)d_in[1];     // (2, E)
    const int*   ea   = (const int*)d_in[2];     // (E, 3)
    const float* femb = (const float*)d_in[3];   // (64, 128)
    const float* cw   = (const float*)d_in[4];   // (2,3,8,4,32,32)
    const float* cr   = (const float*)d_in[5];   // (2,3,128,128)
    const float* cb   = (const float*)d_in[6];   // (2,3,128)
    float* out = (float*)d_out;                  // (180000, 128)

    __half *h0, *h1, *txbase;
    __half2* whb;
    float* invb;
    uint32_t* plb;
    cudaGetSymbolAddress((void**)&h0, g_h0);
    cudaGetSymbolAddress((void**)&h1, g_h1);
    cudaGetSymbolAddress((void**)&txbase, g_txh);
    cudaGetSymbolAddress((void**)&whb, g_wh);
    cudaGetSymbolAddress((void**)&invb, g_inv);
    cudaGetSymbolAddress((void**)&plb, g_plj);
    __half*   txb[3] = { txbase, txbase + TXSZ, txbase + 2 * TXSZ };
    uint32_t* plj[3] = { plb, plb + EE, plb + 2 * EE };
    float*    invj[3] = { invb, invb + RR * N0, invb + 2 * RR * N0 };

    const int tx_blocks = (N0 + 127) / 128;   // 128 nodes per block
    const int M1        = 3 * N0;             // 60000

    Ctx& C = g_ctx;

    // ---- fork from the (captured) default stream ----
    cudaEventRecord(C.eFork, 0);
    cudaStreamWaitEvent(C.sc, C.eFork, 0);
    for (int j = 0; j < 3; j++) cudaStreamWaitEvent(C.sj[j], C.eFork, 0);

    // ---- weight fp16 precompute + femb gemm on sj[0]; eH0 orders both ----
    wcvt_kernel<<<(24 * 16 * 256 + 255) / 256, 256, 0, C.sj[0]>>>(cw);
    gemm_f16<<<(N0 + 127) / 128, 256, 0, C.sj[0]>>>(x, femb, h0, N0, 64);
    cudaEventRecord(C.eH0, C.sj[0]);
    cudaStreamWaitEvent(C.sj[1], C.eH0, 0);
    cudaStreamWaitEvent(C.sj[2], C.eH0, 0);

    // ---- layer 0: tx then fused gemm+agg per j stream ----
    for (int j = 0; j < DD; j++) {
        const __half2* wh = whb + (size_t)(0 * DD + j) * 4 * 4096;
        tx_f16<<<dim3(tx_blocks, 4), 256, 0, C.sj[j]>>>(h0, wh, txb[j]);
    }

    // ---- CSR + inverse counts on side stream (only gemm_agg depends on it) ----
    zero_kernel<<<(DD * RR * N0 + 255) / 256, 256, 0, C.sc>>>();
    count_kernel<<<(EE + 255) / 256, 256, 0, C.sc>>>(ei, ea);
    offsets_kernel<<<(N0 + 255) / 256, 256, 0, C.sc>>>();   // deg from counts (pre-inv)
    inv_kernel<<<(DD * RR * N0 + 255) / 256, 256, 0, C.sc>>>();
    fill_kernel<<<(EE + 255) / 256, 256, 0, C.sc>>>(ei, ea);
    cudaEventRecord(C.eCsr, C.sc);

    for (int j = 0; j < DD; j++) {
        const float* root = cr + (size_t)(0 * DD + j) * (HH * HH);
        const float* bias = cb + (size_t)(0 * DD + j) * HH;
        __half* outr = h1 + (size_t)j * N0 * HH;
        cudaStreamWaitEvent(C.sj[j], C.eCsr, 0);
        gemm_agg<__half><<<(N0 + 127) / 128, 256, DYN_SMEM, C.sj[j]>>>(
            h0, root, bias, txb[j], plj[j], invj[j], outr, N0);
        cudaEventRecord(C.eA0[j], C.sj[j]);
    }

    // ---- layer 1 ----
    // tx reads h1 rows [0,N0) = layer-0 j=0 output -> wait eA0[0]; txb[j]
    // reuse is safe in-stream (gemm_agg0_j finished on sj[j]).
    for (int j = 0; j < DD; j++) {
        const __half2* wh = whb + (size_t)(1 * DD + j) * 4 * 4096;
        if (j != 0) cudaStreamWaitEvent(C.sj[j], C.eA0[0], 0);
        tx_f16<<<dim3(tx_blocks, 4), 256, 0, C.sj[j]>>>(h1, wh, txb[j]);
    }
    for (int j = 0; j < DD; j++) {
        const float* root = cr + (size_t)(1 * DD + j) * (HH * HH);
        const float* bias = cb + (size_t)(1 * DD + j) * HH;
        float* outr = out + (size_t)j * M1 * HH;
        cudaStreamWaitEvent(C.sj[j], C.eA0[(j + 1) % 3], 0);
        cudaStreamWaitEvent(C.sj[j], C.eA0[(j + 2) % 3], 0);
        gemm_agg<float><<<(M1 + 127) / 128, 256, DYN_SMEM, C.sj[j]>>>(
            h1, root, bias, txb[j], plj[j], invj[j], outr, M1);
        cudaEventRecord(C.eDone[j], C.sj[j]);
    }

    // ---- join back to the default stream ----
    for (int j = 0; j < 3; j++) cudaStreamWaitEvent(0, C.eDone[j], 0);
}

// round 16
// speedup vs baseline: 1.4732x; 1.4732x over previous
#include <cuda_runtime.h>
#include <cuda_fp16.h>
#include <cstdint>
#include <type_traits>

// Problem constants (fixed by setup_inputs)
#define N0 20000      // nodes
#define EE 640000     // edges
#define HH 128        // hidden
#define DD 3          // edge-attr dims
#define RR 8          // relations

#define TXSZ ((size_t)RR * N0 * HH)
#define GSSZ ((size_t)3 * N0 * HH)   // layer-1 scratch rows (M1 = 3*N0)

// Scratch (static device globals; no allocation allowed)
__device__ __half   g_h0[(size_t)N0 * HH];        // 5.1 MB  (fp16)
__device__ __half   g_h1[(size_t)3 * N0 * HH];    // 15.4 MB (fp16)
__device__ __half   g_txh[3][TXSZ];               // 3 x 41 MB (per-j, enables overlap)
__device__ __half   g_gs[3][GSSZ];                // 3 x 15.4 MB layer-1 gemm scratch
__device__ float    g_inv[DD * RR * N0];          // 1.9 MB
__device__ int      g_deg[N0];
__device__ int      g_off[N0];
__device__ int      g_pos[N0];
__device__ int      g_total;
__device__ uint32_t g_plj[3][EE];                 // 7.7 MB : per-j packed (r<<29)|src
__device__ __half2  g_wh[24 * 16 * 256];          // 393 KB : fp16 W, sW-interleaved

// ---------------------------------------------------------------------------
__device__ __forceinline__ void mma_f16(float* c, const uint32_t* a, const uint32_t* b) {
    asm volatile("mma.sync.aligned.m16n8k16.row.col.f32.f16.f16.f32 "
                 "{%0,%1,%2,%3},{%4,%5,%6,%7},{%8,%9},{%0,%1,%2,%3};"
                 : "+f"(c[0]), "+f"(c[1]), "+f"(c[2]), "+f"(c[3])
                 : "r"(a[0]), "r"(a[1]), "r"(a[2]), "r"(a[3]), "r"(b[0]), "r"(b[1]));
}

// ---------------------------------------------------------------------------
// Weight precompute: cw fp32 -> g_wh fp16, interleaved for direct sW copies.
// ---------------------------------------------------------------------------
__global__ void wcvt_kernel(const float* __restrict__ cw) {
    int idx = blockIdx.x * blockDim.x + threadIdx.x;
    if (idx >= 24 * 16 * 256) return;
    int col = idx & 255;           // r*32 + d
    int c2  = (idx >> 8) & 15;     // c-pair
    int ljb = idx >> 12;           // (l*3+j)*4 + b
    int b = ljb & 3, lj = ljb >> 2;
    int r = col >> 5, d = col & 31;
    size_t base = ((((size_t)(lj * 8 + r) * 4 + b) * 32 + 2 * c2) * 32) + d;
    g_wh[idx] = __floats2half2_rn(cw[base], cw[base + 32]);
}

// ---------------------------------------------------------------------------
// CSR build + inverse counts
// ---------------------------------------------------------------------------
__global__ void zero_kernel() {
    int i = blockIdx.x * blockDim.x + threadIdx.x;
    if (i < DD * RR * N0) g_inv[i] = 0.f;
    if (i == 0) g_total = 0;
}

__global__ void count_kernel(const int* __restrict__ ei, const int* __restrict__ ea) {
    int e = blockIdx.x * blockDim.x + threadIdx.x;
    if (e >= EE) return;
    int dd = ei[EE + e];
#pragma unroll
    for (int j = 0; j < DD; j++) {
        int r = ea[e * DD + j];
        atomicAdd(&g_inv[(j * RR + r) * N0 + dd], 1.0f);
    }
}

// runs BEFORE inv_kernel: derives deg from the j=0 relation counts
__global__ void offsets_kernel() {
    int d = blockIdx.x * blockDim.x + threadIdx.x;
    if (d >= N0) return;
    float s = 0.f;
#pragma unroll
    for (int r = 0; r < RR; r++) s += g_inv[r * N0 + d];
    int dg = (int)s;
    int o = atomicAdd(&g_total, dg);
    g_deg[d] = dg;
    g_off[d] = o;
    g_pos[d] = o;
}

__global__ void inv_kernel() {
    int i = blockIdx.x * blockDim.x + threadIdx.x;
    if (i < DD * RR * N0) {
        float c = g_inv[i];
        g_inv[i] = 1.0f / fmaxf(c, 1.0f);
    }
}

__global__ void fill_kernel(const int* __restrict__ ei, const int* __restrict__ ea) {
    int e = blockIdx.x * blockDim.x + threadIdx.x;
    if (e >= EE) return;
    uint32_t s = (uint32_t)ei[e];
    int dd = ei[EE + e];
    uint32_t r0 = (uint32_t)ea[e * DD + 0];
    uint32_t r1 = (uint32_t)ea[e * DD + 1];
    uint32_t r2 = (uint32_t)ea[e * DD + 2];
    int p = atomicAdd(&g_pos[dd], 1);
    g_plj[0][p] = (r0 << 29) | s;
    g_plj[1][p] = (r1 << 29) | s;
    g_plj[2][p] = (r2 << 29) | s;
}

// ---------------------------------------------------------------------------
// fp16 GEMM: out[M,128] = A[M,K] @ B[K,128] (+bias). Output fp16 (TO=__half)
// or fp32. TA in {float, __half}.
// 256 thr = 8 warps; block tile 128x128; warp tile 32x64 (2 m16 x 8 n8); k16.
// ---------------------------------------------------------------------------
template <typename TA, typename TO>
__global__ void __launch_bounds__(256, 2)
gemm_f16(const TA* __restrict__ A, const float* __restrict__ B,
         const float* __restrict__ bias, TO* __restrict__ out,
         int M, int K) {
    __shared__ __half  sA[128][40];    // row stride 20 words: conflict-free frag reads
    __shared__ __half2 sB[16][136];    // sB[k/2][n]; row stride 136 words
    int m0   = blockIdx.x * 128;
    int wid  = threadIdx.x >> 5, lane = threadIdx.x & 31;
    int mw   = wid >> 1;            // 0..3 : 32-row slab
    int nw   = wid & 1;             // 0..1 : 64-col slab
    int gid  = lane >> 2;           // 0..7
    int qid  = lane & 3;            // 0..3

    float c[2][8][4];
#pragma unroll
    for (int mt = 0; mt < 2; mt++)
#pragma unroll
        for (int nt = 0; nt < 8; nt++)
#pragma unroll
            for (int q = 0; q < 4; q++) c[mt][nt][q] = 0.f;

    for (int k0 = 0; k0 < K; k0 += 32) {
        // A tile 128x32 -> half
        if constexpr (std::is_same<TA, float>::value) {
#pragma unroll
            for (int it = 0; it < 4; it++) {
                int idx = threadIdx.x + it * 256;
                int m = idx >> 3, k4 = (idx & 7) * 4;
                float4 v = make_float4(0.f, 0.f, 0.f, 0.f);
                if (m0 + m < M) v = *(const float4*)&A[(size_t)(m0 + m) * K + k0 + k4];
                *(__half2*)&sA[m][k4]     = __floats2half2_rn(v.x, v.y);
                *(__half2*)&sA[m][k4 + 2] = __floats2half2_rn(v.z, v.w);
            }
        } else {
#pragma unroll
            for (int it = 0; it < 2; it++) {
                int idx = threadIdx.x + it * 256;
                int m = idx >> 2, k8 = (idx & 3) * 8;
                uint4 v = make_uint4(0, 0, 0, 0);
                if (m0 + m < M) v = *(const uint4*)&A[(size_t)(m0 + m) * K + k0 + k8];
                *(uint2*)&sA[m][k8]     = make_uint2(v.x, v.y);
                *(uint2*)&sA[m][k8 + 4] = make_uint2(v.z, v.w);
            }
        }
        // B tile 32x128 -> 16 k-pair rows x 128 half2
#pragma unroll
        for (int it = 0; it < 2; it++) {
            int idx = threadIdx.x + it * 256;
            int r2 = idx >> 5, c4 = (idx & 31) * 4;
            float4 u = *(const float4*)&B[(size_t)(k0 + 2 * r2) * HH + c4];
            float4 w = *(const float4*)&B[(size_t)(k0 + 2 * r2 + 1) * HH + c4];
            sB[r2][c4 + 0] = __floats2half2_rn(u.x, w.x);
            sB[r2][c4 + 1] = __floats2half2_rn(u.y, w.y);
            sB[r2][c4 + 2] = __floats2half2_rn(u.z, w.z);
            sB[r2][c4 + 3] = __floats2half2_rn(u.w, w.w);
        }
        __syncthreads();
#pragma unroll
        for (int ks = 0; ks < 32; ks += 16) {
            uint32_t a[2][4], b[8][2];
#pragma unroll
            for (int mt = 0; mt < 2; mt++) {
                int r = mw * 32 + mt * 16 + gid;
                a[mt][0] = *(const uint32_t*)&sA[r][ks + qid * 2];
                a[mt][1] = *(const uint32_t*)&sA[r + 8][ks + qid * 2];
                a[mt][2] = *(const uint32_t*)&sA[r][ks + qid * 2 + 8];
                a[mt][3] = *(const uint32_t*)&sA[r + 8][ks + qid * 2 + 8];
            }
            int kp = ks >> 1;   // pair-row base: 0 or 8
#pragma unroll
            for (int nt = 0; nt < 8; nt++) {
                int cn = nw * 64 + nt * 8 + gid;
                b[nt][0] = *(const uint32_t*)&sB[kp + qid][cn];
                b[nt][1] = *(const uint32_t*)&sB[kp + qid + 4][cn];
            }
#pragma unroll
            for (int mt = 0; mt < 2; mt++)
#pragma unroll
                for (int nt = 0; nt < 8; nt++) mma_f16(c[mt][nt], a[mt], b[nt]);
        }
        __syncthreads();
    }

#pragma unroll
    for (int mt = 0; mt < 2; mt++) {
        int row0 = m0 + mw * 32 + mt * 16 + gid;
        int row1 = row0 + 8;
#pragma unroll
        for (int nt = 0; nt < 8; nt++) {
            int col = nw * 64 + nt * 8 + qid * 2;
            float b0 = bias ? bias[col] : 0.f;
            float b1 = bias ? bias[col + 1] : 0.f;
#pragma unroll
            for (int rr = 0; rr < 2; rr++) {
                int row = rr ? row1 : row0;
                if (row >= M) continue;
                float v0 = c[mt][nt][rr * 2 + 0] + b0;
                float v1 = c[mt][nt][rr * 2 + 1] + b1;
                if constexpr (std::is_same<TO, float>::value) {
                    *(float2*)&out[(size_t)row * HH + col] = make_float2(v0, v1);
                } else {
                    *(__half2*)&out[(size_t)row * HH + col] = __floats2half2_rn(v0, v1);
                }
            }
        }
    }
}

// ---------------------------------------------------------------------------
// fp16 tx: grid (ceil(N0/128), 4). Block loads its b-slice of W ONCE (16KB fp16
// copy from g_wh, no cvt), then two 64-node subtiles; staged coalesced epilogue.
// Static smem: sA 5.1KB + sW 16.9KB + sC 16.9KB = 38.9KB.
// ---------------------------------------------------------------------------
__global__ void __launch_bounds__(256, 2)
tx_f16(const __half* __restrict__ h, const __half2* __restrict__ wh, __half* __restrict__ dst) {
    __shared__ __half  sA[64][40];
    __shared__ __half2 sW[16][264];    // k-pairs x 256 cols
    __shared__ __half  sC[32][264];    // 32-row staging
    int base0 = blockIdx.x * 128;
    int b     = blockIdx.y;
    int wid = threadIdx.x >> 5, lane = threadIdx.x & 31;
    int mw  = wid & 1;              // 0..1 : 32-row slab
    int nw  = wid >> 1;             // 0..3 : 64-col slab
    int gid = lane >> 2, qid = lane & 3;

    // load W slice for this b: 4096 half2 = 1024 uint4, 4 per thread (no cvt)
    const __half2* whb = wh + (size_t)b * 4096;
#pragma unroll
    for (int it = 0; it < 4; it++) {
        int idx = threadIdx.x + it * 256;   // [0, 1024)
        int c2 = idx >> 6, u = idx & 63;    // 64 uint4 per 256-half2 row
        *(uint4*)&sW[c2][u * 4] = *(const uint4*)&whb[c2 * 256 + u * 4];
    }

#pragma unroll
    for (int t = 0; t < 2; t++) {
        int n0 = base0 + t * 64;
        // load A: 64x32 halves (256 uint4, 1 per thread)
        {
            int node = threadIdx.x >> 2, k8 = (threadIdx.x & 3) * 8;
            uint4 v = make_uint4(0, 0, 0, 0);
            if (n0 + node < N0) v = *(const uint4*)&h[(size_t)(n0 + node) * HH + b * 32 + k8];
            *(uint2*)&sA[node][k8]     = make_uint2(v.x, v.y);
            *(uint2*)&sA[node][k8 + 4] = make_uint2(v.z, v.w);
        }
        __syncthreads();

        float c[2][8][4];
#pragma unroll
        for (int mt = 0; mt < 2; mt++)
#pragma unroll
            for (int nt = 0; nt < 8; nt++)
#pragma unroll
                for (int q = 0; q < 4; q++) c[mt][nt][q] = 0.f;

#pragma unroll
        for (int ks = 0; ks < 32; ks += 16) {
            uint32_t a[2][4], bb[8][2];
#pragma unroll
            for (int mt = 0; mt < 2; mt++) {
                int r = mw * 32 + mt * 16 + gid;
                a[mt][0] = *(const uint32_t*)&sA[r][ks + qid * 2];
                a[mt][1] = *(const uint32_t*)&sA[r + 8][ks + qid * 2];
                a[mt][2] = *(const uint32_t*)&sA[r][ks + qid * 2 + 8];
                a[mt][3] = *(const uint32_t*)&sA[r + 8][ks + qid * 2 + 8];
            }
            int kp = ks >> 1;
#pragma unroll
            for (int nt = 0; nt < 8; nt++) {
                int cn = nw * 64 + nt * 8 + gid;
                bb[nt][0] = *(const uint32_t*)&sW[kp + qid][cn];
                bb[nt][1] = *(const uint32_t*)&sW[kp + qid + 4][cn];
            }
#pragma unroll
            for (int mt = 0; mt < 2; mt++)
#pragma unroll
                for (int nt = 0; nt < 8; nt++) mma_f16(c[mt][nt], a[mt], bb[nt]);
        }

        // two-phase epilogue: stage 32 rows, coalesced copy, repeat
#pragma unroll
        for (int hf = 0; hf < 2; hf++) {
            __syncthreads();   // MMA done (hf=0) / prior copy done (hf=1)
            if (mw == hf) {
#pragma unroll
                for (int mt = 0; mt < 2; mt++) {
                    int rl = mt * 16 + gid;   // local row within 32-half
#pragma unroll
                    for (int nt = 0; nt < 8; nt++) {
                        int col = nw * 64 + nt * 8 + qid * 2;
                        *(__half2*)&sC[rl][col]     = __floats2half2_rn(c[mt][nt][0], c[mt][nt][1]);
                        *(__half2*)&sC[rl + 8][col] = __floats2half2_rn(c[mt][nt][2], c[mt][nt][3]);
                    }
                }
            }
            __syncthreads();
            // copy: warp w handles rows w, w+8, w+16, w+24 (256 halves = 32 uint4 each)
            int rr = lane >> 2;          // relation 0..7
            int d8 = lane & 3;           // 8-half chunk within 32-d segment
#pragma unroll
            for (int it2 = 0; it2 < 4; it2++) {
                int rl = wid + it2 * 8;
                int node = n0 + hf * 32 + rl;
                if (node < N0) {
                    uint4 v = *(const uint4*)&sC[rl][rr * 32 + d8 * 8];
                    *(uint4*)&dst[((size_t)rr * N0 + node) * HH + b * 32 + d8 * 8] = v;
                }
            }
        }
        __syncthreads();   // sC/sA safe to reuse next subtile
    }
}

// ---------------------------------------------------------------------------
// Aggregation core: CSR edge-gather for one dst row / one lane (4 cols).
// ---------------------------------------------------------------------------
__device__ __forceinline__ void agg_step(float4& acc, uint32_t pk,
                                         const float* __restrict__ inv,
                                         const __half* __restrict__ txh,
                                         int dst, int lane) {
    int r = pk >> 29;
    int s = pk & 0x1FFFFFFF;
    float w = __ldg(&inv[r * N0 + dst]);
    uint2 u = __ldg((const uint2*)&txh[((size_t)r * N0 + s) * HH + lane * 4]);
    float2 f01 = __half22float2(*(__half2*)&u.x);
    float2 f23 = __half22float2(*(__half2*)&u.y);
    acc.x += w * f01.x; acc.y += w * f01.y;
    acc.z += w * f23.x; acc.w += w * f23.y;
}

__device__ __forceinline__ float4 agg_row(const uint32_t* __restrict__ pl,
                                          const float* __restrict__ inv,
                                          const __half* __restrict__ txh,
                                          int dst, int lane) {
    int o = g_off[dst];
    int n = g_deg[dst];
    float4 acc = make_float4(0.f, 0.f, 0.f, 0.f);
    int i = 0;
    for (; i + 8 <= n; i += 8) {
        uint32_t p[8];
#pragma unroll
        for (int u = 0; u < 8; u++) p[u] = __ldg(&pl[o + i + u]);
#pragma unroll
        for (int u = 0; u < 8; u++) agg_step(acc, p[u], inv, txh, dst, lane);
    }
    for (; i + 4 <= n; i += 4) {
        uint32_t p[4];
#pragma unroll
        for (int u = 0; u < 4; u++) p[u] = __ldg(&pl[o + i + u]);
#pragma unroll
        for (int u = 0; u < 4; u++) agg_step(acc, p[u], inv, txh, dst, lane);
    }
    for (; i < n; i++) agg_step(acc, __ldg(&pl[o + i]), inv, txh, dst, lane);
    return acc;
}

// Layer-0: RMW on fp16 h1 (out = relu(out + acc)); warp per dst.
__global__ void agg_rmw_h(__half* __restrict__ out, const __half* __restrict__ txh,
                          const uint32_t* __restrict__ pl, const float* __restrict__ inv) {
    int wid  = (blockIdx.x * blockDim.x + threadIdx.x) >> 5;
    int lane = threadIdx.x & 31;
    if (wid >= N0) return;
    float4 acc = agg_row(pl, inv, txh, wid, lane);
    __half* p = out + (size_t)wid * HH + lane * 4;
    uint2 u = *(uint2*)p;
    float2 c01 = __half22float2(*(__half2*)&u.x);
    float2 c23 = __half22float2(*(__half2*)&u.y);
    __half2 o01 = __floats2half2_rn(fmaxf(c01.x + acc.x, 0.f), fmaxf(c01.y + acc.y, 0.f));
    __half2 o23 = __floats2half2_rn(fmaxf(c23.x + acc.z, 0.f), fmaxf(c23.y + acc.w, 0.f));
    *(uint2*)p = make_uint2(*(uint32_t*)&o01, *(uint32_t*)&o23);
}

// Layer-1 rows < N0: out_f32 = relu(base_f16 + acc) — single write, no RMW.
__global__ void agg_fin(float* __restrict__ out, const __half* __restrict__ base,
                        const __half* __restrict__ txh,
                        const uint32_t* __restrict__ pl, const float* __restrict__ inv) {
    int wid  = (blockIdx.x * blockDim.x + threadIdx.x) >> 5;
    int lane = threadIdx.x & 31;
    if (wid >= N0) return;
    float4 acc = agg_row(pl, inv, txh, wid, lane);
    uint2 u = __ldg((const uint2*)&base[(size_t)wid * HH + lane * 4]);
    float2 c01 = __half22float2(*(__half2*)&u.x);
    float2 c23 = __half22float2(*(__half2*)&u.y);
    *(float4*)&out[(size_t)wid * HH + lane * 4] =
        make_float4(fmaxf(c01.x + acc.x, 0.f), fmaxf(c01.y + acc.y, 0.f),
                    fmaxf(c23.x + acc.z, 0.f), fmaxf(c23.y + acc.w, 0.f));
}

// Layer-1 rows >= N0: out_f32 = relu(base_f16).
__global__ void copy_relu(float* __restrict__ out, const __half* __restrict__ base, int n4) {
    int i = blockIdx.x * blockDim.x + threadIdx.x;
    if (i >= n4) return;
    uint2 u = __ldg((const uint2*)&base[(size_t)i * 4]);
    float2 c01 = __half22float2(*(__half2*)&u.x);
    float2 c23 = __half22float2(*(__half2*)&u.y);
    *(float4*)&out[(size_t)i * 4] =
        make_float4(fmaxf(c01.x, 0.f), fmaxf(c01.y, 0.f), fmaxf(c23.x, 0.f), fmaxf(c23.y, 0.f));
}

// ---------------------------------------------------------------------------
// Streams/events: 4-stream topology (known harness-clean).
// ---------------------------------------------------------------------------
namespace {
struct Ctx {
    cudaStream_t sc, sj[3];
    cudaEvent_t  eFork, eCsr, eH0, eA0[3], eDone[3];
    Ctx() {
        cudaStreamCreateWithFlags(&sc, cudaStreamNonBlocking);
        for (int i = 0; i < 3; i++) cudaStreamCreateWithFlags(&sj[i], cudaStreamNonBlocking);
        cudaEventCreateWithFlags(&eFork, cudaEventDisableTiming);
        cudaEventCreateWithFlags(&eCsr,  cudaEventDisableTiming);
        cudaEventCreateWithFlags(&eH0,   cudaEventDisableTiming);
        for (int i = 0; i < 3; i++) {
            cudaEventCreateWithFlags(&eA0[i],   cudaEventDisableTiming);
            cudaEventCreateWithFlags(&eDone[i], cudaEventDisableTiming);
        }
    }
};
Ctx g_ctx;  // constructed at load time
}

// ---------------------------------------------------------------------------
extern "C" void kernel_launch(void* const* d_in, const int* in_sizes, int n_in,
                              void* d_out, int out_size) {
    const float* x    = (const float*)d_in[0];   // (N0, 64)
    const int*   ei   = (const int*)d_in[1];     // (2, E)
    const int*   ea   = (const int*)d_in[2];     // (E, 3)
    const float* femb = (const float*)d_in[3];   // (64, 128)
    const float* cw   = (const float*)d_in[4];   // (2,3,8,4,32,32)
    const float* cr   = (const float*)d_in[5];   // (2,3,128,128)
    const float* cb   = (const float*)d_in[6];   // (2,3,128)
    float* out = (float*)d_out;                  // (180000, 128)

    __half *h0, *h1, *txbase, *gsbase;
    __half2* whb;
    float* invb;
    uint32_t* plb;
    cudaGetSymbolAddress((void**)&h0, g_h0);
    cudaGetSymbolAddress((void**)&h1, g_h1);
    cudaGetSymbolAddress((void**)&txbase, g_txh);
    cudaGetSymbolAddress((void**)&gsbase, g_gs);
    cudaGetSymbolAddress((void**)&whb, g_wh);
    cudaGetSymbolAddress((void**)&invb, g_inv);
    cudaGetSymbolAddress((void**)&plb, g_plj);
    __half*   txb[3] = { txbase, txbase + TXSZ, txbase + 2 * TXSZ };
    __half*   gsb[3] = { gsbase, gsbase + GSSZ, gsbase + 2 * GSSZ };
    uint32_t* plj[3] = { plb, plb + EE, plb + 2 * EE };
    float*    invj[3] = { invb, invb + RR * N0, invb + 2 * RR * N0 };

    const int agg_blocks = (N0 * 32 + 255) / 256;   // warp per dst
    const int tx_blocks  = (N0 + 127) / 128;        // 128 nodes per block
    const int M1         = 3 * N0;                  // 60000
    const int tail4      = (M1 - N0) * HH / 4;      // copy_relu elements

    Ctx& C = g_ctx;

    // ---- fork from the (captured) default stream ----
    cudaEventRecord(C.eFork, 0);
    cudaStreamWaitEvent(C.sc, C.eFork, 0);
    for (int j = 0; j < 3; j++) cudaStreamWaitEvent(C.sj[j], C.eFork, 0);

    // ---- weight fp16 precompute + femb gemm on sj[0]; eH0 orders both ----
    wcvt_kernel<<<(24 * 16 * 256 + 255) / 256, 256, 0, C.sj[0]>>>(cw);
    gemm_f16<float, __half><<<(N0 + 127) / 128, 256, 0, C.sj[0]>>>(
        x, femb, nullptr, h0, N0, 64);
    cudaEventRecord(C.eH0, C.sj[0]);
    cudaStreamWaitEvent(C.sj[1], C.eH0, 0);
    cudaStreamWaitEvent(C.sj[2], C.eH0, 0);

    // ---- layer 0 tx + root gemms ----
    for (int j = 0; j < DD; j++) {
        const __half2* wh = whb + (size_t)(0 * DD + j) * 4 * 4096;
        tx_f16<<<dim3(tx_blocks, 4), 256, 0, C.sj[j]>>>(h0, wh, txb[j]);
    }
    for (int j = 0; j < DD; j++) {
        const float* root = cr + (size_t)(0 * DD + j) * (HH * HH);
        const float* bias = cb + (size_t)(0 * DD + j) * HH;
        __half* outr = h1 + (size_t)j * N0 * HH;
        gemm_f16<__half, __half><<<(N0 + 127) / 128, 256, 0, C.sj[j]>>>(
            h0, root, bias, outr, N0, HH);
    }

    // ---- CSR + inverse counts on side stream (only agg depends on it) ----
    zero_kernel<<<(DD * RR * N0 + 255) / 256, 256, 0, C.sc>>>();
    count_kernel<<<(EE + 255) / 256, 256, 0, C.sc>>>(ei, ea);
    offsets_kernel<<<(N0 + 255) / 256, 256, 0, C.sc>>>();   // deg from counts (pre-inv)
    inv_kernel<<<(DD * RR * N0 + 255) / 256, 256, 0, C.sc>>>();
    fill_kernel<<<(EE + 255) / 256, 256, 0, C.sc>>>(ei, ea);
    cudaEventRecord(C.eCsr, C.sc);

    // ---- layer 0 agg (RMW on fp16 h1, folds relu; covers all N0 rows) ----
    for (int j = 0; j < DD; j++) {
        __half* outr = h1 + (size_t)j * N0 * HH;
        cudaStreamWaitEvent(C.sj[j], C.eCsr, 0);
        agg_rmw_h<<<agg_blocks, 256, 0, C.sj[j]>>>(outr, txb[j], plj[j], invj[j]);
        cudaEventRecord(C.eA0[j], C.sj[j]);
    }

    // ---- layer 1 ----
    // tx reads h1 rows [0, N0) = layer-0 j=0 output -> start after eA0[0].
    for (int j = 0; j < DD; j++) {
        const __half2* wh = whb + (size_t)(1 * DD + j) * 4 * 4096;
        if (j != 0) cudaStreamWaitEvent(C.sj[j], C.eA0[0], 0);
        tx_f16<<<dim3(tx_blocks, 4), 256, 0, C.sj[j]>>>(h1, wh, txb[j]);
    }
    // root gemm (full h1) -> fp16 scratch; then agg_fin + copy_relu write d_out once
    for (int j = 0; j < DD; j++) {
        const float* root = cr + (size_t)(1 * DD + j) * (HH * HH);
        const float* bias = cb + (size_t)(1 * DD + j) * HH;
        float* outr = out + (size_t)j * M1 * HH;
        cudaStreamWaitEvent(C.sj[j], C.eA0[(j + 1) % 3], 0);
        cudaStreamWaitEvent(C.sj[j], C.eA0[(j + 2) % 3], 0);
        gemm_f16<__half, __half><<<(M1 + 127) / 128, 256, 0, C.sj[j]>>>(
            h1, root, bias, gsb[j], M1, HH);
        agg_fin<<<agg_blocks, 256, 0, C.sj[j]>>>(outr, gsb[j], txb[j], plj[j], invj[j]);
        copy_relu<<<(tail4 + 255) / 256, 256, 0, C.sj[j]>>>(
            outr + (size_t)N0 * HH, gsb[j] + (size_t)N0 * HH, tail4);
        cudaEventRecord(C.eDone[j], C.sj[j]);
    }

    // ---- join back to the default stream ----
    for (int j = 0; j < 3; j++) cudaStreamWaitEvent(0, C.eDone[j], 0);
}